// round 10
// baseline (speedup 1.0000x reference)
#include <cuda_runtime.h>
#include <cuda_fp16.h>
#include <cstdint>

#define TOKENS 2048
#define HIDDEN 4096
#define OUTDIM 4096
#define NLORA  16
#define RANK   16
#define KEXT   (HIDDEN + NLORA * RANK)   // 4352

#define BM 256
#define BN 128
#define BK 64
#define NCH (KEXT / BK)                  // 68

#define STRIDE 144                       // 128B data + 16B pad
#define OFF_A 0
#define OFF_B (BM * STRIDE)              // 36864
#define STG   ((BM + BN) * STRIDE)       // 55296
#define SMEM_BYTES (3 * STG)             // 165888

static_assert(KEXT % BK == 0, "");

__device__ __align__(16) __half g_x[(size_t)TOKENS * KEXT];
__device__ __align__(16) __half g_w[(size_t)OUTDIM * KEXT];
__device__ float g_part[4][TOKENS][RANK];   // per-(kchunk, token, rank) partials
__device__ int g_idx64;

// ---------------- helpers ----------------
__device__ __forceinline__ uint32_t smem_u32(const void* p) {
    uint32_t a;
    asm("{ .reg .u64 t; cvta.to.shared.u64 t, %1; cvt.u32.u64 %0, t; }" : "=r"(a) : "l"(p));
    return a;
}
__device__ __forceinline__ void cp16(uint32_t sdst, const void* gsrc) {
    asm volatile("cp.async.cg.shared.global [%0], [%1], 16;" :: "r"(sdst), "l"(gsrc) : "memory");
}
#define CP_COMMIT() asm volatile("cp.async.commit_group;" ::: "memory")

#define LDSM4(r, a) \
    asm volatile("ldmatrix.sync.aligned.m8n8.x4.shared.b16 {%0,%1,%2,%3}, [%4];" \
        : "=r"((r)[0]), "=r"((r)[1]), "=r"((r)[2]), "=r"((r)[3]) : "r"(a))

__device__ __forceinline__ void mma16816(float* c, const uint32_t* a, uint32_t b0, uint32_t b1) {
    asm volatile(
        "mma.sync.aligned.m16n8k16.row.col.f32.f16.f16.f32 "
        "{%0,%1,%2,%3}, {%4,%5,%6,%7}, {%8,%9}, {%0,%1,%2,%3};"
        : "+f"(c[0]), "+f"(c[1]), "+f"(c[2]), "+f"(c[3])
        : "r"(a[0]), "r"(a[1]), "r"(a[2]), "r"(a[3]), "r"(b0), "r"(b1));
}

// ---------------- prep: detect int32 vs int64 indices ----------------
__global__ void detect_kernel(const int* __restrict__ w) {
    __shared__ int any;
    if (threadIdx.x == 0) any = 0;
    __syncthreads();
    for (int i = threadIdx.x * 2 + 1; i < TOKENS; i += 2 * blockDim.x)
        if (w[i] != 0) any = 1;
    __syncthreads();
    if (threadIdx.x == 0) g_idx64 = (any == 0) ? 1 : 0;
}

__device__ __forceinline__ int load_idx(const void* idx_raw, int t) {
    if (g_idx64) return (int)((const long long*)idx_raw)[t];
    return ((const int*)idx_raw)[t];
}

// ---------------- prep: x -> fp16, LoRA-ext cols zeroed ----------------
__global__ void convert_x_kernel(const float* __restrict__ x) {
    int i = blockIdx.x * blockDim.x + threadIdx.x;   // one 8-col group
    if (i >= TOKENS * (KEXT / 8)) return;
    int row = i / (KEXT / 8);
    int c = (i % (KEXT / 8)) * 8;
    __half h[8];
    if (c < HIDDEN) {
        const float4* src = reinterpret_cast<const float4*>(x + (size_t)row * HIDDEN + c);
        float4 v0 = src[0], v1 = src[1];
        h[0] = __float2half(v0.x); h[1] = __float2half(v0.y);
        h[2] = __float2half(v0.z); h[3] = __float2half(v0.w);
        h[4] = __float2half(v1.x); h[5] = __float2half(v1.y);
        h[6] = __float2half(v1.z); h[7] = __float2half(v1.w);
    } else {
#pragma unroll
        for (int j = 0; j < 8; j++) h[j] = __float2half(0.f);
    }
    *reinterpret_cast<int4*>(g_x + (size_t)row * KEXT + c) = *reinterpret_cast<int4*>(h);
}

// ---------------- prep: W -> fp16, lora_b packed into ext cols ----------------
__global__ void convert_w_kernel(const float* __restrict__ w, const float* __restrict__ lb) {
    int i = blockIdx.x * blockDim.x + threadIdx.x;
    if (i >= OUTDIM * (KEXT / 8)) return;
    int row = i / (KEXT / 8);
    int c = (i % (KEXT / 8)) * 8;
    const float4* src;
    if (c < HIDDEN) {
        src = reinterpret_cast<const float4*>(w + (size_t)row * HIDDEN + c);
    } else {
        int cc = c - HIDDEN;
        int l = cc >> 4, r = cc & 15;    // r = 0 or 8
        src = reinterpret_cast<const float4*>(lb + ((size_t)l * OUTDIM + row) * RANK + r);
    }
    float4 v0 = src[0], v1 = src[1];
    __half h[8];
    h[0] = __float2half(v0.x); h[1] = __float2half(v0.y);
    h[2] = __float2half(v0.z); h[3] = __float2half(v0.w);
    h[4] = __float2half(v1.x); h[5] = __float2half(v1.y);
    h[6] = __float2half(v1.z); h[7] = __float2half(v1.w);
    *reinterpret_cast<int4*>(g_w + (size_t)row * KEXT + c) = *reinterpret_cast<int4*>(h);
}

// ---------------- prep: LoRA rank-16 partial projections ----------------
// block = (lora l, k-chunk kc of 1024). A slice lives in smem; x read once.
__global__ void __launch_bounds__(256, 1)
lora_part_kernel(const float* __restrict__ x,
                 const float* __restrict__ la,
                 const void* __restrict__ idx_raw) {
    extern __shared__ float sh[];                 // [16*1024] A slice, then list
    float* As = sh;                               // 64 KB
    int* list = (int*)(sh + RANK * 1024);         // 8 KB
    __shared__ int cnt;

    const int l = blockIdx.x & 15;
    const int kc = blockIdx.x >> 4;
    const int tid = threadIdx.x, lane = tid & 31, wid = tid >> 5;

    // load A slice: rows r=0..15, cols kc*1024..+1023
    {
        const float4* src = reinterpret_cast<const float4*>(
            la + ((size_t)l * RANK) * HIDDEN + kc * 1024);
        float4* dst = reinterpret_cast<float4*>(As);
        // row r: global offset r*(HIDDEN/4) within src view
        for (int j = tid; j < RANK * 256; j += 256) {
            int r = j >> 8, q = j & 255;
            dst[r * 256 + q] = src[(size_t)r * (HIDDEN / 4) + q];
        }
    }
    if (tid == 0) cnt = 0;
    __syncthreads();

    // build matched-token list
    for (int t = tid; t < TOKENS; t += 256)
        if (load_idx(idx_raw, t) == l) list[atomicAdd(&cnt, 1)] = t;
    __syncthreads();

    const int n = cnt;
    for (int i = wid; i < n; i += 8) {
        const int t = list[i];
        const float4* xp = reinterpret_cast<const float4*>(x + (size_t)t * HIDDEN + kc * 1024);
        float acc[RANK];
#pragma unroll
        for (int r = 0; r < RANK; r++) acc[r] = 0.f;
#pragma unroll
        for (int q = 0; q < 8; q++) {
            float4 xv = xp[lane + 32 * q];
#pragma unroll
            for (int r = 0; r < RANK; r++) {
                float4 av = reinterpret_cast<const float4*>(As)[r * 256 + lane + 32 * q];
                acc[r] += xv.x * av.x + xv.y * av.y + xv.z * av.z + xv.w * av.w;
            }
        }
#pragma unroll
        for (int r = 0; r < RANK; r++) {
#pragma unroll
            for (int o = 16; o > 0; o >>= 1)
                acc[r] += __shfl_xor_sync(0xffffffffu, acc[r], o);
            if (lane == r) g_part[kc][t][r] = acc[r];
        }
    }
}

// ---------------- prep: sum partials, scatter fp16 into x ext cols ----------------
__global__ void scatter_ax_kernel(const void* __restrict__ idx_raw) {
    int t = blockIdx.x * blockDim.x + threadIdx.x;
    if (t >= TOKENS) return;
    int idx = load_idx(idx_raw, t);
    if (idx < 0 || idx >= NLORA) return;
    __half h[16];
#pragma unroll
    for (int r = 0; r < RANK; r++) {
        float s = g_part[0][t][r] + g_part[1][t][r] + g_part[2][t][r] + g_part[3][t][r];
        h[r] = __float2half(s);
    }
    int4* dst = reinterpret_cast<int4*>(g_x + (size_t)t * KEXT + HIDDEN + idx * RANK);
    dst[0] = reinterpret_cast<int4*>(h)[0];
    dst[1] = reinterpret_cast<int4*>(h)[1];
}

// ---------------- main GEMM: out = x_f16 @ w_f16^T (fp32 accum) + bias ----------------
__global__ void __launch_bounds__(512, 1)
gemm_kernel(const float* __restrict__ bias, float* __restrict__ out) {
    extern __shared__ char smem[];
    const uint32_t sb = smem_u32(smem);
    const int tid = threadIdx.x;
    const int lane = tid & 31, wid = tid >> 5;
    const int wm = wid >> 2, wn = wid & 3;          // 4 x 4 warps, warp tile 64 x 32
    const int m0 = (int)(blockIdx.x & 7) * BM;
    const int n0 = (int)(blockIdx.x >> 3) * BN;

    // cp.async slots: 384 rows x 8 segs = 3072 / 512 threads = 6 each
    uint32_t goff[6], soff[6];
    const __half* gbase[6];
#pragma unroll
    for (int j = 0; j < 6; j++) {
        int s = tid + j * 512;
        int row = s >> 3, seg = s & 7;
        uint32_t loc, grow;
        if (row < 256) { gbase[j] = g_x; grow = m0 + row;       loc = OFF_A + row * STRIDE; }
        else           { gbase[j] = g_w; grow = n0 + row - 256; loc = OFF_B + (row - 256) * STRIDE; }
        goff[j] = grow * (uint32_t)KEXT + (uint32_t)seg * 8;
        soff[j] = loc + (uint32_t)seg * 16;
    }

    // ldmatrix lane base offsets (within a stage)
    const uint32_t a_base = (uint32_t)(wm * 64 + (lane & 15)) * STRIDE + ((lane >> 4) << 4);
    const uint32_t b_base = (uint32_t)(wn * 32 + (lane & 15)) * STRIDE + ((lane >> 4) << 4);

    float acc[4][4][4];
#pragma unroll
    for (int a = 0; a < 4; a++)
#pragma unroll
        for (int b = 0; b < 4; b++)
#pragma unroll
            for (int c = 0; c < 4; c++) acc[a][b][c] = 0.f;

    // prologue: stages 0 and 1
#pragma unroll
    for (int p = 0; p < 2; p++) {
        uint32_t s0 = sb + (uint32_t)p * STG;
#pragma unroll
        for (int j = 0; j < 6; j++)
            cp16(s0 + soff[j], gbase[j] + goff[j] + p * BK);
        CP_COMMIT();
    }

#pragma unroll 1
    for (int ks = 0; ks < NCH; ks++) {
        const uint32_t s0 = sb + (uint32_t)(ks % 3) * STG;
        if (ks < NCH - 1) asm volatile("cp.async.wait_group 1;" ::: "memory");
        else              asm volatile("cp.async.wait_group 0;" ::: "memory");
        __syncthreads();

        if (ks + 2 < NCH) {
            const uint32_t sl = sb + (uint32_t)((ks + 2) % 3) * STG;
            const uint32_t kadd = (uint32_t)(ks + 2) * BK;
#pragma unroll
            for (int j = 0; j < 6; j++)
                cp16(sl + soff[j], gbase[j] + goff[j] + kadd);
            CP_COMMIT();
        }

#pragma unroll
        for (int k16 = 0; k16 < 4; k16++) {
            const uint32_t koff = (uint32_t)k16 * 32;
            uint32_t bh[8];
            LDSM4(bh + 0, s0 + OFF_B + b_base + koff);
            LDSM4(bh + 4, s0 + OFF_B + b_base + 16 * STRIDE + koff);
#pragma unroll
            for (int mt = 0; mt < 4; mt++) {
                uint32_t ah[4];
                LDSM4(ah, s0 + OFF_A + a_base + (uint32_t)mt * 16 * STRIDE + koff);
#pragma unroll
                for (int j = 0; j < 4; j++) {
                    const int g = (j >> 1) * 4 + (j & 1);
                    mma16816(acc[mt][j], ah, bh[g], bh[g + 2]);
                }
            }
        }
    }

    // epilogue: acc + bias -> out
    const int orow = m0 + wm * 64 + (lane >> 2);
    const int ocol = n0 + wn * 32 + (lane & 3) * 2;
#pragma unroll
    for (int mt = 0; mt < 4; mt++) {
#pragma unroll
        for (int j = 0; j < 4; j++) {
            const int r0 = orow + mt * 16;
            const int c = ocol + j * 8;
            float2 bv = *reinterpret_cast<const float2*>(bias + c);
            float2 v0, v1;
            v0.x = acc[mt][j][0] + bv.x; v0.y = acc[mt][j][1] + bv.y;
            v1.x = acc[mt][j][2] + bv.x; v1.y = acc[mt][j][3] + bv.y;
            *reinterpret_cast<float2*>(out + (size_t)r0 * OUTDIM + c) = v0;
            *reinterpret_cast<float2*>(out + (size_t)(r0 + 8) * OUTDIM + c) = v1;
        }
    }
}

// ---------------- launch ----------------
extern "C" void kernel_launch(void* const* d_in, const int* in_sizes, int n_in,
                              void* d_out, int out_size) {
    const float* x      = (const float*)d_in[0];
    const float* weight = (const float*)d_in[1];
    const float* bias   = (const float*)d_in[2];
    const float* lora_a = (const float*)d_in[3];
    const float* lora_b = (const float*)d_in[4];
    const void*  indices = d_in[5];
    float* out = (float*)d_out;

    const int lora_smem = RANK * 1024 * 4 + TOKENS * 4;   // 73728
    cudaFuncSetAttribute(gemm_kernel, cudaFuncAttributeMaxDynamicSharedMemorySize, SMEM_BYTES);
    cudaFuncSetAttribute(lora_part_kernel, cudaFuncAttributeMaxDynamicSharedMemorySize, lora_smem);

    detect_kernel<<<1, 256>>>((const int*)indices);
    convert_x_kernel<<<(TOKENS * (KEXT / 8)) / 256, 256>>>(x);
    convert_w_kernel<<<(OUTDIM * (KEXT / 8)) / 256, 256>>>(weight, lora_b);
    lora_part_kernel<<<NLORA * 4, 256, lora_smem>>>(x, lora_a, indices);
    scatter_ax_kernel<<<TOKENS / 256, 256>>>(indices);
    gemm_kernel<<<(TOKENS / BM) * (OUTDIM / BN), 512, SMEM_BYTES>>>(bias, out);
}

// round 11
// speedup vs baseline: 1.4242x; 1.4242x over previous
#include <cuda_runtime.h>
#include <cuda_fp16.h>
#include <cstdint>

#define TOKENS 2048
#define HIDDEN 4096
#define OUTDIM 4096
#define NLORA  16
#define RANK   16
#define KEXT   (HIDDEN + NLORA * RANK)   // 4352

#define BM 256
#define BN 128
#define BK 64
#define NCH (KEXT / BK)                  // 68

#define STRIDE 144                       // 128B data + 16B pad
#define OFF_A 0
#define OFF_B (BM * STRIDE)              // 36864
#define STG   ((BM + BN) * STRIDE)       // 55296
#define SMEM_BYTES (3 * STG)             // 165888

static_assert(KEXT % BK == 0, "");

__device__ __align__(16) __half g_x[(size_t)TOKENS * KEXT];
__device__ __align__(16) __half g_w[(size_t)OUTDIM * KEXT];
__device__ int g_idx64;

// ---------------- helpers ----------------
__device__ __forceinline__ uint32_t smem_u32(const void* p) {
    uint32_t a;
    asm("{ .reg .u64 t; cvta.to.shared.u64 t, %1; cvt.u32.u64 %0, t; }" : "=r"(a) : "l"(p));
    return a;
}
__device__ __forceinline__ void cp16(uint32_t sdst, const void* gsrc) {
    asm volatile("cp.async.cg.shared.global [%0], [%1], 16;" :: "r"(sdst), "l"(gsrc) : "memory");
}
#define CP_COMMIT() asm volatile("cp.async.commit_group;" ::: "memory")

#define LDSM4(r, a) \
    asm volatile("ldmatrix.sync.aligned.m8n8.x4.shared.b16 {%0,%1,%2,%3}, [%4];" \
        : "=r"((r)[0]), "=r"((r)[1]), "=r"((r)[2]), "=r"((r)[3]) : "r"(a))

__device__ __forceinline__ void mma16816(float* c, const uint32_t* a, uint32_t b0, uint32_t b1) {
    asm volatile(
        "mma.sync.aligned.m16n8k16.row.col.f32.f16.f16.f32 "
        "{%0,%1,%2,%3}, {%4,%5,%6,%7}, {%8,%9}, {%0,%1,%2,%3};"
        : "+f"(c[0]), "+f"(c[1]), "+f"(c[2]), "+f"(c[3])
        : "r"(a[0]), "r"(a[1]), "r"(a[2]), "r"(a[3]), "r"(b0), "r"(b1));
}

// ---------------- prep: detect int32 vs int64 indices ----------------
__global__ void detect_kernel(const int* __restrict__ w) {
    __shared__ int any;
    if (threadIdx.x == 0) any = 0;
    __syncthreads();
    for (int i = threadIdx.x * 2 + 1; i < TOKENS; i += 2 * blockDim.x)
        if (w[i] != 0) any = 1;
    __syncthreads();
    if (threadIdx.x == 0) g_idx64 = (any == 0) ? 1 : 0;
}

// ---------------- prep: x -> fp16, LoRA-ext cols zeroed ----------------
__global__ void convert_x_kernel(const float* __restrict__ x) {
    int i = blockIdx.x * blockDim.x + threadIdx.x;   // one 8-col group
    if (i >= TOKENS * (KEXT / 8)) return;
    int row = i / (KEXT / 8);
    int c = (i % (KEXT / 8)) * 8;
    __half h[8];
    if (c < HIDDEN) {
        const float4* src = reinterpret_cast<const float4*>(x + (size_t)row * HIDDEN + c);
        float4 v0 = src[0], v1 = src[1];
        h[0] = __float2half(v0.x); h[1] = __float2half(v0.y);
        h[2] = __float2half(v0.z); h[3] = __float2half(v0.w);
        h[4] = __float2half(v1.x); h[5] = __float2half(v1.y);
        h[6] = __float2half(v1.z); h[7] = __float2half(v1.w);
    } else {
#pragma unroll
        for (int j = 0; j < 8; j++) h[j] = __float2half(0.f);
    }
    *reinterpret_cast<int4*>(g_x + (size_t)row * KEXT + c) = *reinterpret_cast<int4*>(h);
}

// ---------------- prep: W -> fp16, lora_b packed into ext cols ----------------
__global__ void convert_w_kernel(const float* __restrict__ w, const float* __restrict__ lb) {
    int i = blockIdx.x * blockDim.x + threadIdx.x;
    if (i >= OUTDIM * (KEXT / 8)) return;
    int row = i / (KEXT / 8);
    int c = (i % (KEXT / 8)) * 8;
    const float4* src;
    if (c < HIDDEN) {
        src = reinterpret_cast<const float4*>(w + (size_t)row * HIDDEN + c);
    } else {
        int cc = c - HIDDEN;
        int l = cc >> 4, r = cc & 15;    // r = 0 or 8
        src = reinterpret_cast<const float4*>(lb + ((size_t)l * OUTDIM + row) * RANK + r);
    }
    float4 v0 = src[0], v1 = src[1];
    __half h[8];
    h[0] = __float2half(v0.x); h[1] = __float2half(v0.y);
    h[2] = __float2half(v0.z); h[3] = __float2half(v0.w);
    h[4] = __float2half(v1.x); h[5] = __float2half(v1.y);
    h[6] = __float2half(v1.z); h[7] = __float2half(v1.w);
    *reinterpret_cast<int4*>(g_w + (size_t)row * KEXT + c) = *reinterpret_cast<int4*>(h);
}

// ---------------- prep: per-token rank-16 projection -> scattered ext cols ----------------
__global__ void lora_proj_kernel(const float* __restrict__ x,
                                 const float* __restrict__ la,
                                 const void* __restrict__ idx_raw) {
    const int t = blockIdx.x;
    int idx;
    if (g_idx64) idx = (int)((const long long*)idx_raw)[t];
    else         idx = ((const int*)idx_raw)[t];
    if (idx < 0 || idx >= NLORA) return;

    const float4* xr = reinterpret_cast<const float4*>(x + (size_t)t * HIDDEN);
    const float* A = la + (size_t)idx * RANK * HIDDEN;
    float acc[RANK];
#pragma unroll
    for (int r = 0; r < RANK; r++) acc[r] = 0.f;
    for (int j = threadIdx.x; j < HIDDEN / 4; j += 128) {
        float4 xv = xr[j];
#pragma unroll
        for (int r = 0; r < RANK; r++) {
            float4 av = reinterpret_cast<const float4*>(A + (size_t)r * HIDDEN)[j];
            acc[r] += xv.x * av.x + xv.y * av.y + xv.z * av.z + xv.w * av.w;
        }
    }
#pragma unroll
    for (int r = 0; r < RANK; r++)
#pragma unroll
        for (int o = 16; o > 0; o >>= 1)
            acc[r] += __shfl_xor_sync(0xffffffffu, acc[r], o);

    __shared__ float red[4][RANK];
    int w = threadIdx.x >> 5, l = threadIdx.x & 31;
    if (l == 0)
#pragma unroll
        for (int r = 0; r < RANK; r++) red[w][r] = acc[r];
    __syncthreads();
    if (threadIdx.x < RANK) {
        int r = threadIdx.x;
        float s = red[0][r] + red[1][r] + red[2][r] + red[3][r];
        g_x[(size_t)t * KEXT + HIDDEN + idx * RANK + r] = __float2half(s);
    }
}

// ---------------- main GEMM: out = x_f16 @ w_f16^T (fp32 accum) + bias ----------------
__global__ void __launch_bounds__(512, 1)
gemm_kernel(const float* __restrict__ bias, float* __restrict__ out) {
    extern __shared__ char smem[];
    const uint32_t sb = smem_u32(smem);
    const int tid = threadIdx.x;
    const int lane = tid & 31, wid = tid >> 5;
    const int wm = wid >> 2, wn = wid & 3;          // 4 x 4 warps, warp tile 64 x 32
    const int m0 = (int)(blockIdx.x & 7) * BM;
    const int n0 = (int)(blockIdx.x >> 3) * BN;

    // cp.async slots: 384 rows x 8 segs = 3072 / 512 threads = 6 each
    uint32_t goff[6], soff[6];
    const __half* gbase[6];
#pragma unroll
    for (int j = 0; j < 6; j++) {
        int s = tid + j * 512;
        int row = s >> 3, seg = s & 7;
        uint32_t loc, grow;
        if (row < 256) { gbase[j] = g_x; grow = m0 + row;       loc = OFF_A + row * STRIDE; }
        else           { gbase[j] = g_w; grow = n0 + row - 256; loc = OFF_B + (row - 256) * STRIDE; }
        goff[j] = grow * (uint32_t)KEXT + (uint32_t)seg * 8;
        soff[j] = loc + (uint32_t)seg * 16;
    }

    // ldmatrix lane base offsets (within a stage)
    const uint32_t a_base = (uint32_t)(wm * 64 + (lane & 15)) * STRIDE + ((lane >> 4) << 4);
    const uint32_t b_base = (uint32_t)(wn * 32 + (lane & 15)) * STRIDE + ((lane >> 4) << 4);

    float acc[4][4][4];
#pragma unroll
    for (int a = 0; a < 4; a++)
#pragma unroll
        for (int b = 0; b < 4; b++)
#pragma unroll
            for (int c = 0; c < 4; c++) acc[a][b][c] = 0.f;

    // prologue: stages 0 and 1
#pragma unroll
    for (int p = 0; p < 2; p++) {
        uint32_t s0 = sb + (uint32_t)p * STG;
#pragma unroll
        for (int j = 0; j < 6; j++)
            cp16(s0 + soff[j], gbase[j] + goff[j] + p * BK);
        CP_COMMIT();
    }

#pragma unroll 1
    for (int ks = 0; ks < NCH; ks++) {
        const uint32_t s0 = sb + (uint32_t)(ks % 3) * STG;
        if (ks < NCH - 1) asm volatile("cp.async.wait_group 1;" ::: "memory");
        else              asm volatile("cp.async.wait_group 0;" ::: "memory");
        __syncthreads();

        if (ks + 2 < NCH) {
            const uint32_t sl = sb + (uint32_t)((ks + 2) % 3) * STG;
            const uint32_t kadd = (uint32_t)(ks + 2) * BK;
#pragma unroll
            for (int j = 0; j < 6; j++)
                cp16(sl + soff[j], gbase[j] + goff[j] + kadd);
            CP_COMMIT();
        }

#pragma unroll
        for (int k16 = 0; k16 < 4; k16++) {
            const uint32_t koff = (uint32_t)k16 * 32;
            uint32_t bh[8];
            LDSM4(bh + 0, s0 + OFF_B + b_base + koff);
            LDSM4(bh + 4, s0 + OFF_B + b_base + 16 * STRIDE + koff);
#pragma unroll
            for (int mt = 0; mt < 4; mt++) {
                uint32_t ah[4];
                LDSM4(ah, s0 + OFF_A + a_base + (uint32_t)mt * 16 * STRIDE + koff);
#pragma unroll
                for (int j = 0; j < 4; j++) {
                    const int g = (j >> 1) * 4 + (j & 1);
                    mma16816(acc[mt][j], ah, bh[g], bh[g + 2]);
                }
            }
        }
    }

    // epilogue: acc + bias -> out
    const int orow = m0 + wm * 64 + (lane >> 2);
    const int ocol = n0 + wn * 32 + (lane & 3) * 2;
#pragma unroll
    for (int mt = 0; mt < 4; mt++) {
#pragma unroll
        for (int j = 0; j < 4; j++) {
            const int r0 = orow + mt * 16;
            const int c = ocol + j * 8;
            float2 bv = *reinterpret_cast<const float2*>(bias + c);
            float2 v0, v1;
            v0.x = acc[mt][j][0] + bv.x; v0.y = acc[mt][j][1] + bv.y;
            v1.x = acc[mt][j][2] + bv.x; v1.y = acc[mt][j][3] + bv.y;
            *reinterpret_cast<float2*>(out + (size_t)r0 * OUTDIM + c) = v0;
            *reinterpret_cast<float2*>(out + (size_t)(r0 + 8) * OUTDIM + c) = v1;
        }
    }
}

// ---------------- launch ----------------
extern "C" void kernel_launch(void* const* d_in, const int* in_sizes, int n_in,
                              void* d_out, int out_size) {
    const float* x      = (const float*)d_in[0];
    const float* weight = (const float*)d_in[1];
    const float* bias   = (const float*)d_in[2];
    const float* lora_a = (const float*)d_in[3];
    const float* lora_b = (const float*)d_in[4];
    const void*  indices = d_in[5];
    float* out = (float*)d_out;

    cudaFuncSetAttribute(gemm_kernel, cudaFuncAttributeMaxDynamicSharedMemorySize, SMEM_BYTES);

    detect_kernel<<<1, 256>>>((const int*)indices);
    convert_x_kernel<<<(TOKENS * (KEXT / 8)) / 256, 256>>>(x);
    convert_w_kernel<<<(OUTDIM * (KEXT / 8)) / 256, 256>>>(weight, lora_b);
    lora_proj_kernel<<<TOKENS, 128>>>(x, lora_a, indices);
    gemm_kernel<<<(TOKENS / BM) * (OUTDIM / BN), 512, SMEM_BYTES>>>(bias, out);
}